// round 7
// baseline (speedup 1.0000x reference)
#include <cuda_runtime.h>
#include <math.h>

// Problem constants
#define Bn   4
#define Cn   64
#define Hn   128
#define Wn   128
#define HWn  (Hn * Wn)          // 16384
#define K2n  9

// Tiling for the 3x3-conv kernels
#define TH      8
#define TW      32
#define HALO_H  10
#define HALO_W  34
#define HALO_SZ (Cn * HALO_H * HALO_W)   // 21760 floats

// -------- device scratch (static; no runtime allocation) --------
__device__ float g_fused[Bn * Cn * HWn];     // 16 MB
__device__ float g_off[Bn * 2 * K2n * HWn];  // 4.5 MB  (18 channels)
__device__ float g_mod[Bn * K2n * HWn];      // 2.25 MB (9 channels, post-sigmoid)
__device__ float g_wct[K2n * 64 * 64];       // WcT[k][c][oc]

// ============================================================
// Kernel 0: transpose w_conv -> WcT[k][c][oc]
// ============================================================
__global__ void k_wct(const float* __restrict__ wconv) {
    int i = blockIdx.x * 256 + threadIdx.x;
    if (i < K2n * 64 * 64) {
        int oc = i & 63;
        int c  = (i >> 6) & 63;
        int k  = i >> 12;
        g_wct[i] = wconv[(oc * 64 + c) * 9 + k];
    }
}

// ============================================================
// Kernel 1: fused = 1x1 conv over concat(x, ref)  (128 -> 64)
// ============================================================
__global__ void __launch_bounds__(256) k_fused(
    const float* __restrict__ x, const float* __restrict__ ref,
    const float* __restrict__ wcd, const float* __restrict__ bcd)
{
    __shared__ float ws[128 * 65];   // transposed weights ws[ci][co], pad 65
    int tid = threadIdx.x;
    for (int i = tid; i < 128 * 64; i += 256) {
        int co = i >> 7, ci = i & 127;
        ws[ci * 65 + co] = wcd[i];
    }
    __syncthreads();

    int pid = blockIdx.x * 256 + tid;      // [0, 65536)
    int b = pid >> 14;
    int p = pid & (HWn - 1);

    float acc[64];
#pragma unroll
    for (int co = 0; co < 64; co++) acc[co] = bcd[co];

    const float* xb = x   + (size_t)b * Cn * HWn + p;
    const float* rb = ref + (size_t)b * Cn * HWn + p;

    for (int ci = 0; ci < 64; ci++) {
        float v = __ldg(xb + ci * HWn);
        const float* w = ws + ci * 65;
#pragma unroll
        for (int co = 0; co < 64; co++) acc[co] += v * w[co];
    }
    for (int ci = 0; ci < 64; ci++) {
        float v = __ldg(rb + ci * HWn);
        const float* w = ws + (64 + ci) * 65;
#pragma unroll
        for (int co = 0; co < 64; co++) acc[co] += v * w[co];
    }

    float* o = g_fused + (size_t)b * Cn * HWn + p;
#pragma unroll
    for (int co = 0; co < 64; co++) o[co * HWn] = acc[co];
}

// ============================================================
// Kernel 2: off (18ch) + mod (9ch, sigmoid), 3x3 conv pad 1
// smem: halo fused [64][10][34] + weights [576][28]
// ============================================================
__global__ void __launch_bounds__(256) k_offmod(
    const float* __restrict__ wp, const float* __restrict__ bp,
    const float* __restrict__ wm, const float* __restrict__ bm)
{
    extern __shared__ float sm[];
    float* fs  = sm;                // 21760
    float* ws2 = sm + HALO_SZ;      // 576*28 = 16128

    int tid = threadIdx.x;
    int b  = blockIdx.z;
    int h0 = blockIdx.y * TH;
    int w0 = blockIdx.x * TW;

    const float* fb = g_fused + (size_t)b * Cn * HWn;
    for (int i = tid; i < HALO_SZ; i += 256) {
        int ic = i / (HALO_H * HALO_W);
        int rr = (i / HALO_W) % HALO_H;
        int cc = i % HALO_W;
        int gh = h0 - 1 + rr, gw = w0 - 1 + cc;
        float v = 0.f;
        if (gh >= 0 && gh < Hn && gw >= 0 && gw < Wn)
            v = fb[ic * HWn + gh * Wn + gw];
        fs[i] = v;
    }
    for (int i = tid; i < 27 * 576; i += 256) {
        int o = i / 576, j = i - o * 576;
        float v = (o < 18) ? wp[o * 576 + j] : wm[(o - 18) * 576 + j];
        ws2[j * 28 + o] = v;
    }
    __syncthreads();

    int ly = tid >> 5, lx = tid & 31;
    int base = ly * HALO_W + lx;

    float acc[27];
#pragma unroll
    for (int o = 0; o < 27; o++) acc[o] = (o < 18) ? bp[o] : bm[o - 18];

    for (int ic = 0; ic < 64; ic++) {
        float u[9];
#pragma unroll
        for (int t = 0; t < 9; t++)
            u[t] = fs[ic * (HALO_H * HALO_W) + base + (t / 3) * HALO_W + (t % 3)];
#pragma unroll
        for (int t = 0; t < 9; t++) {
            const float* w = ws2 + (ic * 9 + t) * 28;
#pragma unroll
            for (int o = 0; o < 27; o++) acc[o] += u[t] * w[o];
        }
    }

    int h = h0 + ly, w = w0 + lx;
    int pix = h * Wn + w;
#pragma unroll
    for (int o = 0; o < 18; o++)
        g_off[((size_t)b * 18 + o) * HWn + pix] = acc[o];
#pragma unroll
    for (int o = 0; o < 9; o++)
        g_mod[((size_t)b * 9 + o) * HWn + pix] = 1.f / (1.f + expf(-acc[18 + o]));
}

// ============================================================
// Kernel 3: main fused kernel.
// Per pixel: 576-ch conv (tanh) + deform bilinear pos + mod + 64x576 contraction.
// smem: halo 21760 + w-stage 4608 + WcT(k) 4096 floats = 119 KB
// ============================================================
__global__ void __launch_bounds__(256) k_main(
    const float* __restrict__ x, const float* __restrict__ wc,
    const float* __restrict__ bc, float* __restrict__ out)
{
    extern __shared__ float sm[];
    float* fs  = sm;                       // [64][10][34]
    float* wsg = sm + HALO_SZ;             // [576][8]  (8 conv-output rows, g fastest)
    float* wct = wsg + 4608;               // [64 c][64 oc] for current k

    int tid = threadIdx.x;
    int b  = blockIdx.z;
    int h0 = blockIdx.y * TH;
    int w0 = blockIdx.x * TW;

    // --- halo load of fused ---
    const float* fb = g_fused + (size_t)b * Cn * HWn;
    for (int i = tid; i < HALO_SZ; i += 256) {
        int ic = i / (HALO_H * HALO_W);
        int rr = (i / HALO_W) % HALO_H;
        int cc = i % HALO_W;
        int gh = h0 - 1 + rr, gw = w0 - 1 + cc;
        float v = 0.f;
        if (gh >= 0 && gh < Hn && gw >= 0 && gw < Wn)
            v = fb[ic * HWn + gh * Wn + gw];
        fs[i] = v;
    }
    __syncthreads();

    int ly = tid >> 5, lx = tid & 31;
    int h = h0 + ly, w = w0 + lx;
    int pix = h * Wn + w;
    int base = ly * HALO_W + lx;
    const float* xb = x + (size_t)b * Cn * HWn;

    float oacc[64];
#pragma unroll
    for (int i = 0; i < 64; i++) oacc[i] = 0.f;

    for (int k = 0; k < 9; k++) {
        __syncthreads();   // previous k's WcT reads complete before overwrite
        for (int i = tid; i < 4096; i += 256)
            wct[i] = g_wct[k * 4096 + i];

        // ---- sampling metadata for this (k, pixel) ----
        float offx = g_off[((size_t)b * 18 + k) * HWn + pix];
        float offy = g_off[((size_t)b * 18 + 9 + k) * HWn + pix];
        float modk = g_mod[((size_t)b * 9 + k) * HWn + pix];

        float px = (float)(h + 1) + offx + (float)(k / 3 - 1);
        float py = (float)(w + 1) + offy + (float)(k % 3 - 1);
        float fx = floorf(px), fy = floorf(py);
        float qltx = fminf(fmaxf(fx,        0.f), 129.f);
        float qlty = fminf(fmaxf(fy,        0.f), 129.f);
        float qrbx = fminf(fmaxf(fx + 1.f,  0.f), 129.f);
        float qrby = fminf(fmaxf(fy + 1.f,  0.f), 129.f);
        float sx = fminf(fmaxf(px, 0.f), 129.f);
        float sy = fminf(fmaxf(py, 0.f), 129.f);
        float glt = (1.f + qltx - sx) * (1.f + qlty - sy);
        float grb = (1.f - qrbx + sx) * (1.f - qrby + sy);
        float glb = (1.f + qltx - sx) * (1.f - qrby + sy);
        float grt = (1.f - qrbx + sx) * (1.f + qlty - sy);

        int ix0 = (int)qltx, iy0 = (int)qlty;
        int ix1 = (int)qrbx, iy1 = (int)qrby;
        bool vx0 = (ix0 >= 1 && ix0 <= 128), vy0 = (iy0 >= 1 && iy0 <= 128);
        bool vx1 = (ix1 >= 1 && ix1 <= 128), vy1 = (iy1 >= 1 && iy1 <= 128);
        int o00 = (ix0 - 1) * Wn + (iy0 - 1);   // lt
        int o11 = (ix1 - 1) * Wn + (iy1 - 1);   // rb
        int o01 = (ix0 - 1) * Wn + (iy1 - 1);   // lb
        int o10 = (ix1 - 1) * Wn + (iy0 - 1);   // rt
        bool v00 = vx0 && vy0, v11 = vx1 && vy1;
        bool v01 = vx0 && vy1, v10 = vx1 && vy0;

        for (int c0 = 0; c0 < 64; c0 += 8) {
            __syncthreads();   // previous group's wsg reads done
            for (int i = tid; i < 4608; i += 256) {
                int g = i / 576, j = i - g * 576;
                wsg[j * 8 + g] = wc[((size_t)((c0 + g) * 9 + k)) * 576 + j];
            }
            __syncthreads();   // wsg (and, on c0==0, wct) visible

            float acc[8];
#pragma unroll
            for (int g = 0; g < 8; g++) acc[g] = bc[(c0 + g) * 9 + k];

#pragma unroll 2
            for (int ic = 0; ic < 64; ic++) {
                float u[9];
#pragma unroll
                for (int t = 0; t < 9; t++)
                    u[t] = fs[ic * (HALO_H * HALO_W) + base + (t / 3) * HALO_W + (t % 3)];
#pragma unroll
                for (int t = 0; t < 9; t++) {
                    const float4* wv = (const float4*)(wsg + (ic * 9 + t) * 8);
                    float4 a0 = wv[0], a1 = wv[1];
                    acc[0] += u[t] * a0.x; acc[1] += u[t] * a0.y;
                    acc[2] += u[t] * a0.z; acc[3] += u[t] * a0.w;
                    acc[4] += u[t] * a1.x; acc[5] += u[t] * a1.y;
                    acc[6] += u[t] * a1.z; acc[7] += u[t] * a1.w;
                }
            }

            // epilogue: tanh + bilinear pos + mod, then contraction into oacc
#pragma unroll
            for (int g = 0; g < 8; g++) {
                int c = c0 + g;
                const float* xc = xb + c * HWn;
                float p00 = v00 ? __ldg(xc + o00) : 0.f;
                float p11 = v11 ? __ldg(xc + o11) : 0.f;
                float p01 = v01 ? __ldg(xc + o01) : 0.f;
                float p10 = v10 ? __ldg(xc + o10) : 0.f;
                float pos = glt * p00 + grb * p11 + glb * p01 + grt * p10;
                float v = (tanhf(acc[g]) + pos) * modk;

                const float4* wr = (const float4*)(wct + c * 64);
#pragma unroll
                for (int q = 0; q < 16; q++) {
                    float4 wv = wr[q];
                    oacc[q * 4 + 0] += v * wv.x;
                    oacc[q * 4 + 1] += v * wv.y;
                    oacc[q * 4 + 2] += v * wv.z;
                    oacc[q * 4 + 3] += v * wv.w;
                }
            }
        }
    }

    float* ob = out + (size_t)b * 64 * HWn + pix;
#pragma unroll
    for (int oc = 0; oc < 64; oc++) ob[oc * HWn] = oacc[oc];
}

// ============================================================
// launch
// ============================================================
extern "C" void kernel_launch(void* const* d_in, const int* in_sizes, int n_in,
                              void* d_out, int out_size)
{
    const float* x      = (const float*)d_in[0];
    const float* ref    = (const float*)d_in[1];
    const float* w_cd   = (const float*)d_in[2];
    const float* b_cd   = (const float*)d_in[3];
    const float* w_p    = (const float*)d_in[4];
    const float* b_p    = (const float*)d_in[5];
    const float* w_m    = (const float*)d_in[6];
    const float* b_m    = (const float*)d_in[7];
    const float* w_c    = (const float*)d_in[8];
    const float* b_c    = (const float*)d_in[9];
    const float* w_conv = (const float*)d_in[10];
    float* out = (float*)d_out;

    (void)in_sizes; (void)n_in; (void)out_size;

    size_t smem2 = (size_t)(HALO_SZ + 576 * 28) * sizeof(float);       // 151,552
    size_t smem3 = (size_t)(HALO_SZ + 4608 + 4096) * sizeof(float);    // 121,856
    cudaFuncSetAttribute(k_offmod, cudaFuncAttributeMaxDynamicSharedMemorySize, (int)smem2);
    cudaFuncSetAttribute(k_main,   cudaFuncAttributeMaxDynamicSharedMemorySize, (int)smem3);

    k_wct<<<(K2n * 64 * 64 + 255) / 256, 256>>>(w_conv);
    k_fused<<<(Bn * HWn) / 256, 256>>>(x, ref, w_cd, b_cd);

    dim3 grid(Wn / TW, Hn / TH, Bn);   // (4, 16, 4)
    k_offmod<<<grid, 256, smem2>>>(w_p, b_p, w_m, b_m);
    k_main<<<grid, 256, smem3>>>(x, w_c, b_c, out);
}

// round 8
// speedup vs baseline: 1.2641x; 1.2641x over previous
#include <cuda_runtime.h>
#include <math.h>

// Problem constants
#define Bn   4
#define Cn   64
#define Hn   128
#define Wn   128
#define HWn  (Hn * Wn)          // 16384
#define K2n  9

// Tiling
#define TH      8
#define TW      32
#define HALO_H  10
#define HALO_W  34
#define HALO_SZ (Cn * HALO_H * HALO_W)   // 21760 floats

// k_main smem sub-buffer sizes (floats)
#define BB_STRIDE 264                    // im2col / v row stride (256 pix + pad)
#define BB_SZ     (72 * BB_STRIDE)       // 19008
#define WB_STRIDE 68                     // weight-stage row stride (64 m + pad)
#define WB_SZ     (72 * WB_STRIDE)       // 4896
#define META_SZ   (256 * 10)             // 2560
#define SMEM_MAIN (HALO_SZ + BB_SZ + WB_SZ + META_SZ)   // 48224 floats = 192896 B

// -------- device scratch (static; no runtime allocation) --------
__device__ float g_fused[Bn * Cn * HWn];     // 16 MB
__device__ float g_off[Bn * 2 * K2n * HWn];  // 4.5 MB
__device__ float g_mod[Bn * K2n * HWn];      // 2.25 MB
__device__ float g_wct[K2n * 64 * 64];       // WcT[k][c][oc]

// ============================================================
// Kernel 0: transpose w_conv -> WcT[k][c][oc]
// ============================================================
__global__ void k_wct(const float* __restrict__ wconv) {
    int i = blockIdx.x * 256 + threadIdx.x;
    if (i < K2n * 64 * 64) {
        int oc = i & 63;
        int c  = (i >> 6) & 63;
        int k  = i >> 12;
        g_wct[i] = wconv[(oc * 64 + c) * 9 + k];
    }
}

// ============================================================
// Kernel 1: fused = 1x1 conv over concat(x, ref)  (128 -> 64)
// ============================================================
__global__ void __launch_bounds__(256) k_fused(
    const float* __restrict__ x, const float* __restrict__ ref,
    const float* __restrict__ wcd, const float* __restrict__ bcd)
{
    __shared__ float ws[128 * 65];   // transposed weights ws[ci][co]
    int tid = threadIdx.x;
    for (int i = tid; i < 128 * 64; i += 256) {
        int co = i >> 7, ci = i & 127;
        ws[ci * 65 + co] = wcd[i];
    }
    __syncthreads();

    int pid = blockIdx.x * 256 + tid;
    int b = pid >> 14;
    int p = pid & (HWn - 1);

    float acc[64];
#pragma unroll
    for (int co = 0; co < 64; co++) acc[co] = bcd[co];

    const float* xb = x   + (size_t)b * Cn * HWn + p;
    const float* rb = ref + (size_t)b * Cn * HWn + p;

    for (int ci = 0; ci < 64; ci++) {
        float v = __ldg(xb + ci * HWn);
        const float* w = ws + ci * 65;
#pragma unroll
        for (int co = 0; co < 64; co++) acc[co] += v * w[co];
    }
    for (int ci = 0; ci < 64; ci++) {
        float v = __ldg(rb + ci * HWn);
        const float* w = ws + (64 + ci) * 65;
#pragma unroll
        for (int co = 0; co < 64; co++) acc[co] += v * w[co];
    }

    float* o = g_fused + (size_t)b * Cn * HWn + p;
#pragma unroll
    for (int co = 0; co < 64; co++) o[co * HWn] = acc[co];
}

// ============================================================
// Kernel 2: off (18ch) + mod (9ch, sigmoid), 3x3 conv pad 1
// ============================================================
__global__ void __launch_bounds__(256) k_offmod(
    const float* __restrict__ wp, const float* __restrict__ bp,
    const float* __restrict__ wm, const float* __restrict__ bm)
{
    extern __shared__ float sm[];
    float* fs  = sm;
    float* ws2 = sm + HALO_SZ;      // 576*28

    int tid = threadIdx.x;
    int b  = blockIdx.z;
    int h0 = blockIdx.y * TH;
    int w0 = blockIdx.x * TW;

    const float* fb = g_fused + (size_t)b * Cn * HWn;
    for (int i = tid; i < HALO_SZ; i += 256) {
        int ic = i / (HALO_H * HALO_W);
        int rr = (i / HALO_W) % HALO_H;
        int cc = i % HALO_W;
        int gh = h0 - 1 + rr, gw = w0 - 1 + cc;
        float v = 0.f;
        if (gh >= 0 && gh < Hn && gw >= 0 && gw < Wn)
            v = fb[ic * HWn + gh * Wn + gw];
        fs[i] = v;
    }
    for (int i = tid; i < 27 * 576; i += 256) {
        int o = i / 576, j = i - o * 576;
        float v = (o < 18) ? wp[o * 576 + j] : wm[(o - 18) * 576 + j];
        ws2[j * 28 + o] = v;
    }
    __syncthreads();

    int ly = tid >> 5, lx = tid & 31;
    int base = ly * HALO_W + lx;

    float acc[27];
#pragma unroll
    for (int o = 0; o < 27; o++) acc[o] = (o < 18) ? bp[o] : bm[o - 18];

    for (int ic = 0; ic < 64; ic++) {
        float u[9];
#pragma unroll
        for (int t = 0; t < 9; t++)
            u[t] = fs[ic * (HALO_H * HALO_W) + base + (t / 3) * HALO_W + (t % 3)];
#pragma unroll
        for (int t = 0; t < 9; t++) {
            const float* w = ws2 + (ic * 9 + t) * 28;
#pragma unroll
            for (int o = 0; o < 27; o++) acc[o] += u[t] * w[o];
        }
    }

    int h = h0 + ly, w = w0 + lx;
    int pix = h * Wn + w;
#pragma unroll
    for (int o = 0; o < 18; o++)
        g_off[((size_t)b * 18 + o) * HWn + pix] = acc[o];
#pragma unroll
    for (int o = 0; o < 9; o++)
        g_mod[((size_t)b * 9 + o) * HWn + pix] = 1.f / (1.f + expf(-acc[18 + o]));
}

// ============================================================
// Kernel 3: main — two register-tiled GEMMs per k.
//   GEMM1: conv  acc[8m x 8p] over K=576 (8 chunks of 72)
//   epilogue: tanh + bilinear + mod -> vbuf[64][256]
//   GEMM2: oacc[8oc x 8p] += WcT_k @ vbuf
// ============================================================
__global__ void __launch_bounds__(256, 1) k_main(
    const float* __restrict__ x, const float* __restrict__ wc,
    const float* __restrict__ bc, float* __restrict__ out)
{
    extern __shared__ float sm[];
    float* fs   = sm;                      // [64][10][34]
    float* bbuf = sm + HALO_SZ;            // [72][264] im2col chunk (aliased vbuf)
    float* wbuf = bbuf + BB_SZ;            // [72][68] weight stage (aliased WcT)
    float* meta = wbuf + WB_SZ;            // [256][10]
    float* vbuf = bbuf;                    // [64][264]

    int tid = threadIdx.x;
    int b  = blockIdx.z;
    int h0 = blockIdx.y * TH;
    int w0 = blockIdx.x * TW;

    int mw  = tid & 7;                     // m-group (8 groups of 8)
    int nw  = tid >> 3;                    // n-group (32 groups of 8 pixels)
    int mw8 = mw << 3;
    int p0  = ((nw >> 2) << 5) + ((nw & 3) << 3);   // first of 8 consecutive pixels

    // --- halo load ---
    const float* fb = g_fused + (size_t)b * Cn * HWn;
    for (int i = tid; i < HALO_SZ; i += 256) {
        int ic = i / (HALO_H * HALO_W);
        int rr = (i / HALO_W) % HALO_H;
        int cc = i % HALO_W;
        int gh = h0 - 1 + rr, gw = w0 - 1 + cc;
        float v = 0.f;
        if (gh >= 0 && gh < Hn && gw >= 0 && gw < Wn)
            v = fb[ic * HWn + gh * Wn + gw];
        fs[i] = v;
    }

    int ly = tid >> 5, lx = tid & 31;      // this thread's metadata pixel
    int h = h0 + ly, w = w0 + lx;
    int pix = h * Wn + w;
    int basep = ly * HALO_W + lx;
    const float* xb = x + (size_t)b * Cn * HWn;

    float oacc[8][8];
#pragma unroll
    for (int i = 0; i < 8; i++)
#pragma unroll
        for (int j = 0; j < 8; j++) oacc[i][j] = 0.f;

    for (int k = 0; k < 9; k++) {
        __syncthreads();   // prev k's GEMM2 / meta reads done; halo ready (k=0)

        // ---- sampling metadata for pixel `tid` ----
        {
            float offx = g_off[((size_t)b * 18 + k) * HWn + pix];
            float offy = g_off[((size_t)b * 18 + 9 + k) * HWn + pix];
            float modk = g_mod[((size_t)b * 9 + k) * HWn + pix];

            float px = (float)(h + 1) + offx + (float)(k / 3 - 1);
            float py = (float)(w + 1) + offy + (float)(k % 3 - 1);
            float fx = floorf(px), fy = floorf(py);
            float qltx = fminf(fmaxf(fx,       0.f), 129.f);
            float qlty = fminf(fmaxf(fy,       0.f), 129.f);
            float qrbx = fminf(fmaxf(fx + 1.f, 0.f), 129.f);
            float qrby = fminf(fmaxf(fy + 1.f, 0.f), 129.f);
            float sx = fminf(fmaxf(px, 0.f), 129.f);
            float sy = fminf(fmaxf(py, 0.f), 129.f);
            float glt = (1.f + qltx - sx) * (1.f + qlty - sy);
            float grb = (1.f - qrbx + sx) * (1.f - qrby + sy);
            float glb = (1.f + qltx - sx) * (1.f - qrby + sy);
            float grt = (1.f - qrbx + sx) * (1.f + qlty - sy);

            int ix0 = (int)qltx, iy0 = (int)qlty;
            int ix1 = (int)qrbx, iy1 = (int)qrby;
            bool vx0 = (ix0 >= 1 && ix0 <= 128), vy0 = (iy0 >= 1 && iy0 <= 128);
            bool vx1 = (ix1 >= 1 && ix1 <= 128), vy1 = (iy1 >= 1 && iy1 <= 128);
            bool v00 = vx0 && vy0, v11 = vx1 && vy1;
            bool v01 = vx0 && vy1, v10 = vx1 && vy0;
            int o00 = v00 ? ((ix0 - 1) * Wn + (iy0 - 1)) : 0;
            int o11 = v11 ? ((ix1 - 1) * Wn + (iy1 - 1)) : 0;
            int o01 = v01 ? ((ix0 - 1) * Wn + (iy1 - 1)) : 0;
            int o10 = v10 ? ((ix1 - 1) * Wn + (iy0 - 1)) : 0;

            float* mt = meta + tid * 10;
            mt[0] = v00 ? glt : 0.f;
            mt[1] = v11 ? grb : 0.f;
            mt[2] = v01 ? glb : 0.f;
            mt[3] = v10 ? grt : 0.f;
            mt[4] = __int_as_float(o00);
            mt[5] = __int_as_float(o11);
            mt[6] = __int_as_float(o01);
            mt[7] = __int_as_float(o10);
            mt[8] = modk;
        }

        // ---- GEMM1: conv accumulators ----
        float acc[8][8];
#pragma unroll
        for (int i = 0; i < 8; i++) {
            float bi = bc[(mw8 + i) * 9 + k];
#pragma unroll
            for (int j = 0; j < 8; j++) acc[i][j] = bi;
        }

        for (int s = 0; s < 8; s++) {
            __syncthreads();   // prev chunk reads done (s=0: meta store visible too)

            // build im2col chunk: bbuf[r][p=tid], r = lic*9 + t, ic = s*8+lic
            {
                int r = 0;
#pragma unroll
                for (int lic = 0; lic < 8; lic++) {
                    int icb = (s * 8 + lic) * (HALO_H * HALO_W) + basep;
#pragma unroll
                    for (int t = 0; t < 9; t++) {
                        bbuf[r * BB_STRIDE + tid] = fs[icb + (t / 3) * HALO_W + (t % 3)];
                        r++;
                    }
                }
            }
            // stage weights: wbuf[r][m] = wc[(m*9+k)*576 + s*72 + r]
            for (int i = tid; i < 64 * 72; i += 256) {
                int m = i / 72, r = i - m * 72;
                wbuf[r * WB_STRIDE + m] = wc[((size_t)(m * 9 + k)) * 576 + s * 72 + r];
            }
            __syncthreads();

#pragma unroll 4
            for (int r = 0; r < 72; r++) {
                float4 b0 = *(const float4*)(bbuf + r * BB_STRIDE + p0);
                float4 b1 = *(const float4*)(bbuf + r * BB_STRIDE + p0 + 4);
                float4 a0 = *(const float4*)(wbuf + r * WB_STRIDE + mw8);
                float4 a1 = *(const float4*)(wbuf + r * WB_STRIDE + mw8 + 4);
                float av[8] = {a0.x, a0.y, a0.z, a0.w, a1.x, a1.y, a1.z, a1.w};
                float bv[8] = {b0.x, b0.y, b0.z, b0.w, b1.x, b1.y, b1.z, b1.w};
#pragma unroll
                for (int i = 0; i < 8; i++)
#pragma unroll
                    for (int j = 0; j < 8; j++)
                        acc[i][j] += av[i] * bv[j];
            }
        }

        __syncthreads();   // bbuf/wbuf reads done -> safe to write vbuf / WcT

        // stage WcT_k into wbuf: [c][oc]
        for (int i = tid; i < 4096; i += 256)
            wbuf[(i >> 6) * WB_STRIDE + (i & 63)] = g_wct[k * 4096 + i];

        // ---- epilogue: tanh + bilinear + mod -> vbuf[c][p] ----
#pragma unroll
        for (int j = 0; j < 8; j++) {
            int p = p0 + j;
            const float* mt = meta + p * 10;
            float glt = mt[0], grb = mt[1], glb = mt[2], grt = mt[3];
            int o00 = __float_as_int(mt[4]);
            int o11 = __float_as_int(mt[5]);
            int o01 = __float_as_int(mt[6]);
            int o10 = __float_as_int(mt[7]);
            float modk = mt[8];
#pragma unroll
            for (int i = 0; i < 8; i++) {
                const float* xc = xb + (mw8 + i) * HWn;
                float pos = glt * __ldg(xc + o00) + grb * __ldg(xc + o11)
                          + glb * __ldg(xc + o01) + grt * __ldg(xc + o10);
                float v = (tanhf(acc[i][j]) + pos) * modk;
                vbuf[(mw8 + i) * BB_STRIDE + p] = v;
            }
        }
        __syncthreads();

        // ---- GEMM2: oacc += WcT_k @ v ----
#pragma unroll 4
        for (int c = 0; c < 64; c++) {
            float4 b0 = *(const float4*)(vbuf + c * BB_STRIDE + p0);
            float4 b1 = *(const float4*)(vbuf + c * BB_STRIDE + p0 + 4);
            float4 a0 = *(const float4*)(wbuf + c * WB_STRIDE + mw8);
            float4 a1 = *(const float4*)(wbuf + c * WB_STRIDE + mw8 + 4);
            float av[8] = {a0.x, a0.y, a0.z, a0.w, a1.x, a1.y, a1.z, a1.w};
            float bv[8] = {b0.x, b0.y, b0.z, b0.w, b1.x, b1.y, b1.z, b1.w};
#pragma unroll
            for (int i = 0; i < 8; i++)
#pragma unroll
                for (int j = 0; j < 8; j++)
                    oacc[i][j] += av[i] * bv[j];
        }
    }

    // ---- store output ----
    int oh = h0 + (p0 >> 5), ow = w0 + (p0 & 31);
    float* ob = out + (size_t)b * 64 * HWn + oh * Wn + ow;
#pragma unroll
    for (int i = 0; i < 8; i++) {
        float4 r0 = make_float4(oacc[i][0], oacc[i][1], oacc[i][2], oacc[i][3]);
        float4 r1 = make_float4(oacc[i][4], oacc[i][5], oacc[i][6], oacc[i][7]);
        float* dst = ob + (mw8 + i) * HWn;
        *(float4*)(dst)     = r0;
        *(float4*)(dst + 4) = r1;
    }
}

// ============================================================
// launch
// ============================================================
extern "C" void kernel_launch(void* const* d_in, const int* in_sizes, int n_in,
                              void* d_out, int out_size)
{
    const float* x      = (const float*)d_in[0];
    const float* ref    = (const float*)d_in[1];
    const float* w_cd   = (const float*)d_in[2];
    const float* b_cd   = (const float*)d_in[3];
    const float* w_p    = (const float*)d_in[4];
    const float* b_p    = (const float*)d_in[5];
    const float* w_m    = (const float*)d_in[6];
    const float* b_m    = (const float*)d_in[7];
    const float* w_c    = (const float*)d_in[8];
    const float* b_c    = (const float*)d_in[9];
    const float* w_conv = (const float*)d_in[10];
    float* out = (float*)d_out;

    (void)in_sizes; (void)n_in; (void)out_size;

    size_t smem2 = (size_t)(HALO_SZ + 576 * 28) * sizeof(float);   // 151,552
    size_t smem3 = (size_t)SMEM_MAIN * sizeof(float);              // 192,896
    cudaFuncSetAttribute(k_offmod, cudaFuncAttributeMaxDynamicSharedMemorySize, (int)smem2);
    cudaFuncSetAttribute(k_main,   cudaFuncAttributeMaxDynamicSharedMemorySize, (int)smem3);

    k_wct<<<(K2n * 64 * 64 + 255) / 256, 256>>>(w_conv);
    k_fused<<<(Bn * HWn) / 256, 256>>>(x, ref, w_cd, b_cd);

    dim3 grid(Wn / TW, Hn / TH, Bn);   // (4, 16, 4)
    k_offmod<<<grid, 256, smem2>>>(w_p, b_p, w_m, b_m);
    k_main<<<grid, 256, smem3>>>(x, w_c, b_c, out);
}